// round 16
// baseline (speedup 1.0000x reference)
#include <cuda_runtime.h>
#include <cuda_bf16.h>
#include <cstdint>

// CenterLoss: out = mean_b ||features[b] - centers[labels[b]]||^2
// B = 65536, D = 256, C = 100000, LAMBDA_C = 1.0.
//
// R16 = R12 (best: 18.9us) with compute-side micro-tuning only.
// Memory engine byte-identical to R12: cp.async per lane, depth-3 ring
// (2 stages of 2KB in flight per warp), 8 warps/block, 8 rows/warp,
// 1024 blocks. R10-R15 established: outstanding bytes/SM (>=100KB) far
// exceeds the ~10KB BW-delay product at the achieved 4.8TB/s -> the
// stream+gather LTS/HBM service rate is the roof, not MLP/occupancy.
// Changes vs R12: dual accumulators (serial FMA chain 32->16 cyc/row),
// marginally cheaper epilogue.
// L2 policy: centers evict_last (labels repeat across graph replays ->
// L2-resident; wall 18.9 < ncu 25.2 confirms), features evict_first.
// Block partial -> last-block-done double reduction; wrapping atomic counter
// self-resets across replays.

#define D 256
#define ROW_BYTES (D * 4)          // 1024
#define WARPS_PER_BLOCK 8
#define ROWS_PER_WARP 8
#define NBLOCKS 1024               // 1024 * 8 * 8 = 65536 = B
#define DEPTH 3

__device__ float g_partials[NBLOCKS];
__device__ unsigned int g_ctr = 0;

__device__ __forceinline__ void cp16(uint32_t dst_smem, const void* src, unsigned long long pol) {
    asm volatile("cp.async.cg.shared.global.L2::cache_hint [%0], [%1], 16, %2;"
                 :: "r"(dst_smem), "l"(src), "l"(pol) : "memory");
}

__global__ __launch_bounds__(WARPS_PER_BLOCK * 32)
void center_loss_fused(const float* __restrict__ feat,
                       const int* __restrict__ labels,
                       const float* __restrict__ centers,
                       float* __restrict__ out, int B) {
    // Per-warp triple-buffered staging: [feat 1KB | center 1KB] per stage.
    __shared__ __align__(16) char cpbuf[WARPS_PER_BLOCK][DEPTH][2 * ROW_BYTES];

    const int warp = threadIdx.x >> 5;
    const int lane = threadIdx.x & 31;
    const int row0 = (blockIdx.x * WARPS_PER_BLOCK + warp) * ROWS_PER_WARP;

    unsigned long long pol_last, pol_first;
    asm volatile("createpolicy.fractional.L2::evict_last.b64 %0, 1.0;"  : "=l"(pol_last));
    asm volatile("createpolicy.fractional.L2::evict_first.b64 %0, 1.0;" : "=l"(pol_first));

    // Preload all 8 labels (2 broadcast int4 loads).
    int labs[ROWS_PER_WARP];
    #pragma unroll
    for (int q = 0; q < 2; q++) {
        int4 l4 = *reinterpret_cast<const int4*>(labels + row0 + q * 4);
        labs[q * 4 + 0] = l4.x; labs[q * 4 + 1] = l4.y;
        labs[q * 4 + 2] = l4.z; labs[q * 4 + 3] = l4.w;
    }

    const char* fbase = reinterpret_cast<const char*>(feat) + (size_t)row0 * ROW_BYTES;
    const char* cbase = reinterpret_cast<const char*>(centers);
    const uint32_t sbase = (uint32_t)__cvta_generic_to_shared(&cpbuf[warp][0][0]);
    const int lo = lane * 16;

    // Issue one stage's 4 cp.asyncs + commit. Ring slot = j % DEPTH.
    auto issue = [&](int j) {
        const uint32_t d = sbase + (uint32_t)(j % DEPTH) * (2 * ROW_BYTES);
        const char* fs = fbase + (size_t)j * ROW_BYTES;
        const char* cs = cbase + (size_t)labs[j] * ROW_BYTES;
        cp16(d + lo,                   fs + lo,       pol_first);
        cp16(d + 512 + lo,             fs + 512 + lo, pol_first);
        cp16(d + ROW_BYTES + lo,       cs + lo,       pol_last);
        cp16(d + ROW_BYTES + 512 + lo, cs + 512 + lo, pol_last);
        asm volatile("cp.async.commit_group;" ::: "memory");
    };

    // Prologue: two stages in flight.
    issue(0);
    issue(1);

    float acc0 = 0.0f, acc1 = 0.0f;
    #pragma unroll
    for (int j = 0; j < ROWS_PER_WARP; j++) {
        if (j + 2 < ROWS_PER_WARP) {
            issue(j + 2);
            asm volatile("cp.async.wait_group 2;" ::: "memory");
        } else if (j + 1 < ROWS_PER_WARP) {
            asm volatile("cp.async.wait_group 1;" ::: "memory");
        } else {
            asm volatile("cp.async.wait_group 0;" ::: "memory");
        }
        // Consume stage j: lane reads exactly the 2x16B (feat) + 2x16B (cent)
        // it copied itself -> no cross-lane visibility needed.
        const char* d = &cpbuf[warp][j % DEPTH][0];
        float4 a0 = *reinterpret_cast<const float4*>(d + lo);
        float4 a1 = *reinterpret_cast<const float4*>(d + 512 + lo);
        float4 b0 = *reinterpret_cast<const float4*>(d + ROW_BYTES + lo);
        float4 b1 = *reinterpret_cast<const float4*>(d + ROW_BYTES + 512 + lo);
        float t;
        // Two independent accumulator chains (16-cyc dep chain per row).
        t = a0.x - b0.x; acc0 = fmaf(t, t, acc0);
        t = a1.x - b1.x; acc1 = fmaf(t, t, acc1);
        t = a0.y - b0.y; acc0 = fmaf(t, t, acc0);
        t = a1.y - b1.y; acc1 = fmaf(t, t, acc1);
        t = a0.z - b0.z; acc0 = fmaf(t, t, acc0);
        t = a1.z - b1.z; acc1 = fmaf(t, t, acc1);
        t = a0.w - b0.w; acc0 = fmaf(t, t, acc0);
        t = a1.w - b1.w; acc1 = fmaf(t, t, acc1);
    }
    float acc = acc0 + acc1;

    // Warp reduction (fixed tree -> deterministic)
    #pragma unroll
    for (int o = 16; o > 0; o >>= 1)
        acc += __shfl_xor_sync(0xFFFFFFFFu, acc, o);

    __shared__ float s[WARPS_PER_BLOCK];
    __shared__ bool is_last;
    if (lane == 0) s[warp] = acc;
    __syncthreads();

    if (threadIdx.x == 0) {
        float t = 0.0f;
        #pragma unroll
        for (int i = 0; i < WARPS_PER_BLOCK; i++) t += s[i];
        g_partials[blockIdx.x] = t;
        __threadfence();
        unsigned int old = atomicInc(&g_ctr, gridDim.x - 1);  // wraps -> replay-safe
        is_last = (old == gridDim.x - 1);
    }
    __syncthreads();

    if (!is_last) return;

    // Last block: deterministic double-precision reduction of 1024 partials.
    __shared__ double sd[256];
    const volatile float* vp = g_partials;
    double t = 0.0;
    #pragma unroll 4
    for (int i = threadIdx.x; i < NBLOCKS; i += 256)
        t += (double)vp[i];
    sd[threadIdx.x] = t;
    __syncthreads();
    #pragma unroll
    for (int stride = 128; stride > 0; stride >>= 1) {
        if (threadIdx.x < stride) sd[threadIdx.x] += sd[threadIdx.x + stride];
        __syncthreads();
    }
    if (threadIdx.x == 0)
        out[0] = (float)(sd[0] / (double)B);   // LAMBDA_C = 1.0
}

extern "C" void kernel_launch(void* const* d_in, const int* in_sizes, int n_in,
                              void* d_out, int out_size) {
    const float* feat    = (const float*)d_in[0];
    const int*   labels  = (const int*)d_in[1];
    const float* centers = (const float*)d_in[2];
    float*       out     = (float*)d_out;

    const int B = in_sizes[1];   // 65536

    center_loss_fused<<<NBLOCKS, WARPS_PER_BLOCK * 32>>>(feat, labels, centers, out, B);
}

// round 17
// speedup vs baseline: 1.2162x; 1.2162x over previous
#include <cuda_runtime.h>
#include <cuda_bf16.h>
#include <cstdint>

// CenterLoss: out = mean_b ||features[b] - centers[labels[b]]||^2
// B = 65536, D = 256, C = 100000, LAMBDA_C = 1.0.
//
// R17 = R12 verbatim (session-best: 18.912us, rel_err 0.0).
// R16's accumulator interleave pushed regs 48->64, occ 45%, +4us: reverted.
//
// Final architecture and why:
//  - cp.async per lane (4x16B per stage) into a DEPTH-3 SMEM ring: loads have
//    ZERO destination registers, so ptxas cannot serialize them to save regs
//    (the R3/R5/R6/R8 failure mode). Two 2KB stages in flight per warp.
//  - 8 warps/block, 8 rows/warp, 1024 blocks; each lane consumes exactly the
//    bytes it copied -> no cross-lane sync inside the pipeline.
//  - L2 policy: centers evict_last (labels identical across graph replays ->
//    gathered ~48MB of center rows stays L2-resident; wall 18.9us vs 25.2us
//    under ncu --cache-control all proves the dividend), features
//    evict_first (one-pass 64MB stream must not thrash centers).
//  - Roofline: ~120MB compulsory traffic; measured ~4.8TB/s cold is the
//    LTS/HBM service rate for this stream+random-1KB-gather mix (six configs
//    R10-R16 with 24-70% occ and 2-6KB/warp depth all converge here).
//  - Epilogue: block partial -> last-block-done double-precision reduction;
//    atomicInc wrapping at gridDim self-resets -> graph-replay safe, exact
//    (rel_err 0.0), no second kernel launch (saved ~10us vs R1).

#define D 256
#define ROW_BYTES (D * 4)          // 1024
#define WARPS_PER_BLOCK 8
#define ROWS_PER_WARP 8
#define NBLOCKS 1024               // 1024 * 8 * 8 = 65536 = B
#define DEPTH 3

__device__ float g_partials[NBLOCKS];
__device__ unsigned int g_ctr = 0;

__device__ __forceinline__ void cp16(uint32_t dst_smem, const void* src, unsigned long long pol) {
    asm volatile("cp.async.cg.shared.global.L2::cache_hint [%0], [%1], 16, %2;"
                 :: "r"(dst_smem), "l"(src), "l"(pol) : "memory");
}

__global__ __launch_bounds__(WARPS_PER_BLOCK * 32)
void center_loss_fused(const float* __restrict__ feat,
                       const int* __restrict__ labels,
                       const float* __restrict__ centers,
                       float* __restrict__ out, int B) {
    // Per-warp triple-buffered staging: [feat 1KB | center 1KB] per stage.
    __shared__ __align__(16) char cpbuf[WARPS_PER_BLOCK][DEPTH][2 * ROW_BYTES];

    const int warp = threadIdx.x >> 5;
    const int lane = threadIdx.x & 31;
    const int row0 = (blockIdx.x * WARPS_PER_BLOCK + warp) * ROWS_PER_WARP;

    unsigned long long pol_last, pol_first;
    asm volatile("createpolicy.fractional.L2::evict_last.b64 %0, 1.0;"  : "=l"(pol_last));
    asm volatile("createpolicy.fractional.L2::evict_first.b64 %0, 1.0;" : "=l"(pol_first));

    // Preload all 8 labels (2 broadcast int4 loads).
    int labs[ROWS_PER_WARP];
    #pragma unroll
    for (int q = 0; q < 2; q++) {
        int4 l4 = *reinterpret_cast<const int4*>(labels + row0 + q * 4);
        labs[q * 4 + 0] = l4.x; labs[q * 4 + 1] = l4.y;
        labs[q * 4 + 2] = l4.z; labs[q * 4 + 3] = l4.w;
    }

    const char* fbase = reinterpret_cast<const char*>(feat) + (size_t)row0 * ROW_BYTES;
    const char* cbase = reinterpret_cast<const char*>(centers);
    const uint32_t sbase = (uint32_t)__cvta_generic_to_shared(&cpbuf[warp][0][0]);
    const int lo = lane * 16;

    // Issue one stage's 4 cp.asyncs + commit. Ring slot = j % DEPTH.
    auto issue = [&](int j) {
        const uint32_t d = sbase + (uint32_t)(j % DEPTH) * (2 * ROW_BYTES);
        const char* fs = fbase + (size_t)j * ROW_BYTES;
        const char* cs = cbase + (size_t)labs[j] * ROW_BYTES;
        cp16(d + lo,                   fs + lo,       pol_first);
        cp16(d + 512 + lo,             fs + 512 + lo, pol_first);
        cp16(d + ROW_BYTES + lo,       cs + lo,       pol_last);
        cp16(d + ROW_BYTES + 512 + lo, cs + 512 + lo, pol_last);
        asm volatile("cp.async.commit_group;" ::: "memory");
    };

    // Prologue: two stages in flight.
    issue(0);
    issue(1);

    float acc = 0.0f;
    #pragma unroll
    for (int j = 0; j < ROWS_PER_WARP; j++) {
        if (j + 2 < ROWS_PER_WARP) {
            issue(j + 2);
            asm volatile("cp.async.wait_group 2;" ::: "memory");
        } else if (j + 1 < ROWS_PER_WARP) {
            asm volatile("cp.async.wait_group 1;" ::: "memory");
        } else {
            asm volatile("cp.async.wait_group 0;" ::: "memory");
        }
        // Consume stage j: lane reads exactly the 2x16B (feat) + 2x16B (cent)
        // it copied itself -> no cross-lane visibility needed.
        const char* d = &cpbuf[warp][j % DEPTH][0];
        float4 a0 = *reinterpret_cast<const float4*>(d + lo);
        float4 a1 = *reinterpret_cast<const float4*>(d + 512 + lo);
        float4 b0 = *reinterpret_cast<const float4*>(d + ROW_BYTES + lo);
        float4 b1 = *reinterpret_cast<const float4*>(d + ROW_BYTES + 512 + lo);
        float t;
        t = a0.x - b0.x; acc = fmaf(t, t, acc);
        t = a0.y - b0.y; acc = fmaf(t, t, acc);
        t = a0.z - b0.z; acc = fmaf(t, t, acc);
        t = a0.w - b0.w; acc = fmaf(t, t, acc);
        t = a1.x - b1.x; acc = fmaf(t, t, acc);
        t = a1.y - b1.y; acc = fmaf(t, t, acc);
        t = a1.z - b1.z; acc = fmaf(t, t, acc);
        t = a1.w - b1.w; acc = fmaf(t, t, acc);
    }

    // Warp reduction (fixed tree -> deterministic)
    #pragma unroll
    for (int o = 16; o > 0; o >>= 1)
        acc += __shfl_xor_sync(0xFFFFFFFFu, acc, o);

    __shared__ float s[WARPS_PER_BLOCK];
    __shared__ bool is_last;
    if (lane == 0) s[warp] = acc;
    __syncthreads();

    if (threadIdx.x == 0) {
        float t = 0.0f;
        #pragma unroll
        for (int i = 0; i < WARPS_PER_BLOCK; i++) t += s[i];
        g_partials[blockIdx.x] = t;
        __threadfence();
        unsigned int old = atomicInc(&g_ctr, gridDim.x - 1);  // wraps -> replay-safe
        is_last = (old == gridDim.x - 1);
    }
    __syncthreads();

    if (!is_last) return;

    // Last block: deterministic double-precision reduction of 1024 partials.
    __shared__ double sd[256];
    const volatile float* vp = g_partials;
    double t = 0.0;
    #pragma unroll 4
    for (int i = threadIdx.x; i < NBLOCKS; i += 256)
        t += (double)vp[i];
    sd[threadIdx.x] = t;
    __syncthreads();
    #pragma unroll
    for (int stride = 128; stride > 0; stride >>= 1) {
        if (threadIdx.x < stride) sd[threadIdx.x] += sd[threadIdx.x + stride];
        __syncthreads();
    }
    if (threadIdx.x == 0)
        out[0] = (float)(sd[0] / (double)B);   // LAMBDA_C = 1.0
}

extern "C" void kernel_launch(void* const* d_in, const int* in_sizes, int n_in,
                              void* d_out, int out_size) {
    const float* feat    = (const float*)d_in[0];
    const int*   labels  = (const int*)d_in[1];
    const float* centers = (const float*)d_in[2];
    float*       out     = (float*)d_out;

    const int B = in_sizes[1];   // 65536

    center_loss_fused<<<NBLOCKS, WARPS_PER_BLOCK * 32>>>(feat, labels, centers, out, B);
}